// round 15
// baseline (speedup 1.0000x reference)
#include <cuda_runtime.h>
#include <cuda_bf16.h>
#include <cstdint>

#define N_PTS 384
#define DIM 128
#define MARGIN 0.3f
#define K2_GRID 128
#define K2_BLK 384
#define ANCH 3

// Scratch (no allocations allowed).
__device__ float g_gram[N_PTS * N_PTS];
__device__ float g_nrm[N_PTS];

// Accumulators: reset by the last-ticket block each run (graph-replay safe).
__device__ float g_acc[2];
__device__ unsigned int g_ticket;

// ---------------------------------------------------------------------------
// K1: Gram matrix, 32x32 tiles. B-tile staged in smem (column access needs
// banking); A-tile read straight from L1 (2 distinct rows per warp per load).
// Diagonal blocks emit norms. Signals PDL dependents after stores.
// ---------------------------------------------------------------------------
__global__ __launch_bounds__(256) void gram_kernel(const float* __restrict__ E,
                                                   float* __restrict__ G,
                                                   float* __restrict__ nrm) {
    __shared__ float Bs[32][132];

    const int bi = blockIdx.y * 32;
    const int bj = blockIdx.x * 32;
    const int t = threadIdx.x;

    const float4* E4 = reinterpret_cast<const float4*>(E);

    // Stage B tile only (16.9 KB).
    for (int v = t; v < 1024; v += 256) {
        int r = v >> 5;
        int c4 = v & 31;
        *reinterpret_cast<float4*>(&Bs[r][c4 * 4]) = E4[(bj + r) * 32 + c4];
    }
    __syncthreads();

    const int ti = t >> 4;
    const int tj = t & 15;

    const float4* Ar0 = E4 + (bi + ti) * 32;        // row ti
    const float4* Ar1 = E4 + (bi + ti + 16) * 32;   // row ti+16

    float acc00 = 0.f, acc01 = 0.f, acc10 = 0.f, acc11 = 0.f;

#pragma unroll 8
    for (int k4 = 0; k4 < 32; k4++) {
        float4 a0 = __ldg(&Ar0[k4]);
        float4 a1 = __ldg(&Ar1[k4]);
        float4 b0 = *reinterpret_cast<const float4*>(&Bs[tj][k4 * 4]);
        float4 b1 = *reinterpret_cast<const float4*>(&Bs[tj + 16][k4 * 4]);
        acc00 = fmaf(a0.x, b0.x, acc00);
        acc00 = fmaf(a0.y, b0.y, acc00);
        acc00 = fmaf(a0.z, b0.z, acc00);
        acc00 = fmaf(a0.w, b0.w, acc00);
        acc01 = fmaf(a0.x, b1.x, acc01);
        acc01 = fmaf(a0.y, b1.y, acc01);
        acc01 = fmaf(a0.z, b1.z, acc01);
        acc01 = fmaf(a0.w, b1.w, acc01);
        acc10 = fmaf(a1.x, b0.x, acc10);
        acc10 = fmaf(a1.y, b0.y, acc10);
        acc10 = fmaf(a1.z, b0.z, acc10);
        acc10 = fmaf(a1.w, b0.w, acc10);
        acc11 = fmaf(a1.x, b1.x, acc11);
        acc11 = fmaf(a1.y, b1.y, acc11);
        acc11 = fmaf(a1.z, b1.z, acc11);
        acc11 = fmaf(a1.w, b1.w, acc11);
    }

    const int gi0 = bi + ti, gi1 = bi + ti + 16;
    const int gj0 = bj + tj, gj1 = bj + tj + 16;
    G[gi0 * N_PTS + gj0] = acc00;
    G[gi0 * N_PTS + gj1] = acc01;
    G[gi1 * N_PTS + gj0] = acc10;
    G[gi1 * N_PTS + gj1] = acc11;

    if (blockIdx.x == blockIdx.y && ti == tj) {
        nrm[gi0] = acc00;
        nrm[gi1] = acc11;
    }

    __threadfence();
    asm volatile("griddepcontrol.launch_dependents;");
}

// ---------------------------------------------------------------------------
// K2: 128 blocks x 384 threads, 3 anchors each. The pos/neg compaction
// (labels-only) runs entirely BEFORE the PDL wait; post-wait work is just
// load -> 3 FMA -> scatter to precomputed slots -> pair loop.
// ---------------------------------------------------------------------------
__global__ __launch_bounds__(K2_BLK) void triplet_kernel(
    const float* __restrict__ G,
    const float* __restrict__ nrm,
    const int* __restrict__ labels,
    float* __restrict__ out, int out_size) {

    const int blk = blockIdx.x;
    const int t = threadIdx.x;
    const int lane = t & 31;
    const int warp = t >> 5;       // 12 warps
    const int a0 = blk * ANCH;

    __shared__ float spos[ANCH][N_PTS];
    __shared__ float sneg[ANCH][N_PTS];
    __shared__ int cnts[ANCH][2];
    __shared__ float wl[12], wc[12];

    // ---- Prologue: labels + full compaction bookkeeping (pre-wait) ----
    if (t < ANCH * 2) ((int*)cnts)[t] = 0;
    const int lt_label = labels[t];
    int la[ANCH];
#pragma unroll
    for (int k = 0; k < ANCH; k++) la[k] = labels[a0 + k];
    const unsigned ltm = (1u << lane) - 1u;
    __syncthreads();   // cnts zeroed

    bool same[ANCH];
    int slot[ANCH];
#pragma unroll
    for (int k = 0; k < ANCH; k++) {
        same[k] = (lt_label == la[k]);
        unsigned ms = __ballot_sync(0xFFFFFFFFu, same[k]);
        unsigned md = ~ms;
        int bp = 0, bn = 0;
        if (lane == 0) {
            bp = atomicAdd(&cnts[k][0], __popc(ms));
            bn = atomicAdd(&cnts[k][1], __popc(md));
        }
        bp = __shfl_sync(0xFFFFFFFFu, bp, 0);
        bn = __shfl_sync(0xFFFFFFFFu, bn, 0);
        slot[k] = same[k] ? (bp + __popc(ms & ltm)) : (bn + __popc(md & ltm));
    }
    __syncthreads();   // all atomics done -> P/M final
    int P[ANCH], M[ANCH];
#pragma unroll
    for (int k = 0; k < ANCH; k++) { P[k] = cnts[k][0]; M[k] = cnts[k][1]; }

    // ---- Wait for K1's G / nrm ----
    asm volatile("griddepcontrol.wait;" ::: "memory");

    // Batched loads, one latency exposure.
    const float nt = nrm[t];
    float gv[ANCH], na[ANCH];
#pragma unroll
    for (int k = 0; k < ANCH; k++) gv[k] = G[(a0 + k) * N_PTS + t];
#pragma unroll
    for (int k = 0; k < ANCH; k++) na[k] = nrm[a0 + k];

    // Scatter distances to precomputed slots.
#pragma unroll
    for (int k = 0; k < ANCH; k++) {
        const float dj = na[k] + nt - 2.f * gv[k];
        if (same[k]) spos[k][slot[k]] = dj;
        else         sneg[k][slot[k]] = dj;
    }
    __syncthreads();

    // ---- Pair loops ----
    float loss = 0.f, cnt = 0.f;
#pragma unroll
    for (int k = 0; k < ANCH; k++) {
        if (t < M[k]) {
            const float dnm = sneg[k][t] - MARGIN;
            for (int p = 0; p < P[k]; p++) {
                float L = spos[k][p] - dnm;
                if (L > 0.f && L < MARGIN) { loss += L; cnt += 1.f; }
            }
        }
    }

    // ---- Reduce + accumulate + last-block writeout ----
#pragma unroll
    for (int off = 16; off > 0; off >>= 1) {
        loss += __shfl_down_sync(0xFFFFFFFFu, loss, off);
        cnt  += __shfl_down_sync(0xFFFFFFFFu, cnt,  off);
    }
    if (lane == 0) { wl[warp] = loss; wc[warp] = cnt; }
    __syncthreads();

    if (t == 0) {
        float l = 0.f, c = 0.f;
#pragma unroll
        for (int w = 0; w < 12; w++) { l += wl[w]; c += wc[w]; }
        atomicAdd(&g_acc[0], l);
        atomicAdd(&g_acc[1], c);
        __threadfence();
        unsigned int done = atomicAdd(&g_ticket, 1u);
        if ((done % K2_GRID) == K2_GRID - 1) {
            __threadfence();
            out[0] = g_acc[0];
            out[1] = g_acc[1];
            for (int k = 2; k < out_size; k++) out[k] = 0.f;
            g_acc[0] = 0.f;
            g_acc[1] = 0.f;
        }
    }
}

extern "C" void kernel_launch(void* const* d_in, const int* in_sizes, int n_in,
                              void* d_out, int out_size) {
    const float* embeddings = (const float*)d_in[0];
    const int* labels = (const int*)d_in[1];
    float* out = (float*)d_out;

    float *G, *nrm;
    cudaGetSymbolAddress((void**)&G, g_gram);
    cudaGetSymbolAddress((void**)&nrm, g_nrm);

    dim3 grid1(12, 12);
    gram_kernel<<<grid1, 256>>>(embeddings, G, nrm);

    cudaLaunchConfig_t cfg = {};
    cfg.gridDim = dim3(K2_GRID);
    cfg.blockDim = dim3(K2_BLK);
    cfg.dynamicSmemBytes = 0;
    cfg.stream = 0;
    cudaLaunchAttribute attr[1];
    attr[0].id = cudaLaunchAttributeProgrammaticStreamSerialization;
    attr[0].val.programmaticStreamSerializationAllowed = 1;
    cfg.attrs = attr;
    cfg.numAttrs = 1;
    cudaLaunchKernelEx(&cfg, triplet_kernel, (const float*)G, (const float*)nrm,
                       labels, out, out_size);
}

// round 17
// speedup vs baseline: 1.0490x; 1.0490x over previous
#include <cuda_runtime.h>
#include <cuda_bf16.h>
#include <cstdint>

#define N_PTS 384
#define DIM 128
#define MARGIN 0.3f
#define K1_BLK 512
#define K2_GRID 128
#define K2_BLK 384
#define ANCH 3

// Scratch (no allocations allowed).
__device__ float g_gram[N_PTS * N_PTS];
__device__ float g_nrm[N_PTS];

// Accumulators: reset by the last-ticket block each run (graph-replay safe).
__device__ float g_acc[2];
__device__ unsigned int g_ticket;

// ---------------------------------------------------------------------------
// K1: Gram matrix, 32x32 tiles, 512 threads (2 outputs/thread, 16 warps/SM).
// Both tiles staged in smem (proven-fast R6 memory scheme). Diagonal blocks
// emit norms. Signals PDL dependents after stores.
// ---------------------------------------------------------------------------
__global__ __launch_bounds__(K1_BLK) void gram_kernel(const float* __restrict__ E,
                                                      float* __restrict__ G,
                                                      float* __restrict__ nrm) {
    __shared__ float As[32][132];
    __shared__ float Bs[32][132];

    const int bi = blockIdx.y * 32;
    const int bj = blockIdx.x * 32;
    const int t = threadIdx.x;

    const float4* E4 = reinterpret_cast<const float4*>(E);
    for (int v = t; v < 1024; v += K1_BLK) {
        int r = v >> 5;
        int c4 = v & 31;
        *reinterpret_cast<float4*>(&As[r][c4 * 4]) = E4[(bi + r) * 32 + c4];
        *reinterpret_cast<float4*>(&Bs[r][c4 * 4]) = E4[(bj + r) * 32 + c4];
    }
    __syncthreads();

    // 2 outputs per thread: (ti, tj) and (ti, tj+16).
    const int ti = t >> 4;       // 0..31
    const int tj = t & 15;       // 0..15

    float acc0 = 0.f, acc1 = 0.f;

#pragma unroll 8
    for (int k4 = 0; k4 < 32; k4++) {
        float4 a  = *reinterpret_cast<const float4*>(&As[ti][k4 * 4]);
        float4 b0 = *reinterpret_cast<const float4*>(&Bs[tj][k4 * 4]);
        float4 b1 = *reinterpret_cast<const float4*>(&Bs[tj + 16][k4 * 4]);
        acc0 = fmaf(a.x, b0.x, acc0);
        acc0 = fmaf(a.y, b0.y, acc0);
        acc0 = fmaf(a.z, b0.z, acc0);
        acc0 = fmaf(a.w, b0.w, acc0);
        acc1 = fmaf(a.x, b1.x, acc1);
        acc1 = fmaf(a.y, b1.y, acc1);
        acc1 = fmaf(a.z, b1.z, acc1);
        acc1 = fmaf(a.w, b1.w, acc1);
    }

    const int gi = bi + ti;
    G[gi * N_PTS + bj + tj]      = acc0;
    G[gi * N_PTS + bj + tj + 16] = acc1;

    if (blockIdx.x == blockIdx.y) {
        if (ti == tj)      nrm[gi] = acc0;
        if (ti == tj + 16) nrm[gi] = acc1;
    }

    __threadfence();
    asm volatile("griddepcontrol.launch_dependents;");
}

// ---------------------------------------------------------------------------
// K2: 128 blocks x 384 threads, 3 anchors each. Labels-only compaction runs
// entirely BEFORE the PDL wait; post-wait: load -> FMA -> scatter -> pairs.
// ---------------------------------------------------------------------------
__global__ __launch_bounds__(K2_BLK) void triplet_kernel(
    const float* __restrict__ G,
    const float* __restrict__ nrm,
    const int* __restrict__ labels,
    float* __restrict__ out, int out_size) {

    const int blk = blockIdx.x;
    const int t = threadIdx.x;
    const int lane = t & 31;
    const int warp = t >> 5;       // 12 warps
    const int a0 = blk * ANCH;

    __shared__ float spos[ANCH][N_PTS];
    __shared__ float sneg[ANCH][N_PTS];
    __shared__ int cnts[ANCH][2];
    __shared__ float wl[12], wc[12];

    // ---- Prologue: labels + full compaction bookkeeping (pre-wait) ----
    if (t < ANCH * 2) ((int*)cnts)[t] = 0;
    const int lt_label = labels[t];
    int la[ANCH];
#pragma unroll
    for (int k = 0; k < ANCH; k++) la[k] = labels[a0 + k];
    const unsigned ltm = (1u << lane) - 1u;
    __syncthreads();   // cnts zeroed

    bool same[ANCH];
    int slot[ANCH];
#pragma unroll
    for (int k = 0; k < ANCH; k++) {
        same[k] = (lt_label == la[k]);
        unsigned ms = __ballot_sync(0xFFFFFFFFu, same[k]);
        unsigned md = ~ms;
        int bp = 0, bn = 0;
        if (lane == 0) {
            bp = atomicAdd(&cnts[k][0], __popc(ms));
            bn = atomicAdd(&cnts[k][1], __popc(md));
        }
        bp = __shfl_sync(0xFFFFFFFFu, bp, 0);
        bn = __shfl_sync(0xFFFFFFFFu, bn, 0);
        slot[k] = same[k] ? (bp + __popc(ms & ltm)) : (bn + __popc(md & ltm));
    }
    __syncthreads();   // all atomics done -> P/M final
    int P[ANCH], M[ANCH];
#pragma unroll
    for (int k = 0; k < ANCH; k++) { P[k] = cnts[k][0]; M[k] = cnts[k][1]; }

    // ---- Wait for K1's G / nrm ----
    asm volatile("griddepcontrol.wait;" ::: "memory");

    // Batched loads, one latency exposure.
    const float nt = nrm[t];
    float gv[ANCH], na[ANCH];
#pragma unroll
    for (int k = 0; k < ANCH; k++) gv[k] = G[(a0 + k) * N_PTS + t];
#pragma unroll
    for (int k = 0; k < ANCH; k++) na[k] = nrm[a0 + k];

    // Scatter distances to precomputed slots.
#pragma unroll
    for (int k = 0; k < ANCH; k++) {
        const float dj = na[k] + nt - 2.f * gv[k];
        if (same[k]) spos[k][slot[k]] = dj;
        else         sneg[k][slot[k]] = dj;
    }
    __syncthreads();

    // ---- Pair loops ----
    float loss = 0.f, cnt = 0.f;
#pragma unroll
    for (int k = 0; k < ANCH; k++) {
        if (t < M[k]) {
            const float dnm = sneg[k][t] - MARGIN;
            for (int p = 0; p < P[k]; p++) {
                float L = spos[k][p] - dnm;
                if (L > 0.f && L < MARGIN) { loss += L; cnt += 1.f; }
            }
        }
    }

    // ---- Reduce + accumulate + last-block writeout ----
#pragma unroll
    for (int off = 16; off > 0; off >>= 1) {
        loss += __shfl_down_sync(0xFFFFFFFFu, loss, off);
        cnt  += __shfl_down_sync(0xFFFFFFFFu, cnt,  off);
    }
    if (lane == 0) { wl[warp] = loss; wc[warp] = cnt; }
    __syncthreads();

    if (t == 0) {
        float l = 0.f, c = 0.f;
#pragma unroll
        for (int w = 0; w < 12; w++) { l += wl[w]; c += wc[w]; }
        atomicAdd(&g_acc[0], l);
        atomicAdd(&g_acc[1], c);
        __threadfence();
        unsigned int done = atomicAdd(&g_ticket, 1u);
        if ((done % K2_GRID) == K2_GRID - 1) {
            __threadfence();
            out[0] = g_acc[0];
            out[1] = g_acc[1];
            for (int k = 2; k < out_size; k++) out[k] = 0.f;
            g_acc[0] = 0.f;
            g_acc[1] = 0.f;
        }
    }
}

extern "C" void kernel_launch(void* const* d_in, const int* in_sizes, int n_in,
                              void* d_out, int out_size) {
    const float* embeddings = (const float*)d_in[0];
    const int* labels = (const int*)d_in[1];
    float* out = (float*)d_out;

    float *G, *nrm;
    cudaGetSymbolAddress((void**)&G, g_gram);
    cudaGetSymbolAddress((void**)&nrm, g_nrm);

    dim3 grid1(12, 12);
    gram_kernel<<<grid1, K1_BLK>>>(embeddings, G, nrm);

    cudaLaunchConfig_t cfg = {};
    cfg.gridDim = dim3(K2_GRID);
    cfg.blockDim = dim3(K2_BLK);
    cfg.dynamicSmemBytes = 0;
    cfg.stream = 0;
    cudaLaunchAttribute attr[1];
    attr[0].id = cudaLaunchAttributeProgrammaticStreamSerialization;
    attr[0].val.programmaticStreamSerializationAllowed = 1;
    cfg.attrs = attr;
    cfg.numAttrs = 1;
    cudaLaunchKernelEx(&cfg, triplet_kernel, (const float*)G, (const float*)nrm,
                       labels, out, out_size);
}